// round 6
// baseline (speedup 1.0000x reference)
#include <cuda_runtime.h>
#include <math.h>
#include <stdint.h>

#define B_TOK 16384
#define D_DIM 1024
#define H_DIM 256
#define E_NUM 8
#define TM    64
#define NTHR  256

// 2-stage ring: stage = A(64x32 = 8KB) + B(256x32 = 32KB) = 40KB
#define ST_A_SZ 8192
#define ST_SZ   40960
#define DYN_SMEM 81920   // 2 stages; E1 h-staging (67.6KB) reuses it after drain

// ---------------- device scratch ----------------
__device__ int   g_cnt[E_NUM];
__device__ int   g_tok[E_NUM][B_TOK];          // tok*2 + rank
__device__ float g_wgt[E_NUM][B_TOK];
__device__ float g_w1t[(size_t)E_NUM * H_DIM * D_DIM];   // [e][h][d] tf32
__device__ float g_w2t[(size_t)E_NUM * D_DIM * H_DIM];   // [e][d][h] tf32
__device__ float g_h[(size_t)E_NUM * B_TOK * H_DIM];     // gelu(h) tf32, [e][pos][256]
__device__ float g_part[2ull * B_TOK * D_DIM];           // rank partials

// ---------------- helpers ----------------
__device__ __forceinline__ uint32_t smem_u32(const void* p) {
    uint32_t r;
    asm("{.reg .u64 t; cvta.to.shared.u64 t,%1; cvt.u32.u64 %0,t;}" : "=r"(r) : "l"(p));
    return r;
}
__device__ __forceinline__ uint32_t f2tf(float f) {
    uint32_t u; asm("cvt.rna.tf32.f32 %0,%1;" : "=r"(u) : "f"(f)); return u;
}
__device__ __forceinline__ void cp16(uint32_t s, const void* g) {
    asm volatile("cp.async.cg.shared.global [%0],[%1],16;" :: "r"(s), "l"(g));
}
__device__ __forceinline__ void cp_commit() {
    asm volatile("cp.async.commit_group;" ::: "memory");
}
template <int N> __device__ __forceinline__ void cp_wait() {
    asm volatile("cp.async.wait_group %0;" :: "n"(N) : "memory");
}
__device__ __forceinline__ void ldsm4(uint32_t* r, uint32_t a) {
    asm volatile("ldmatrix.sync.aligned.m8n8.x4.shared.b16 {%0,%1,%2,%3},[%4];"
                 : "=r"(r[0]), "=r"(r[1]), "=r"(r[2]), "=r"(r[3]) : "r"(a));
}
__device__ __forceinline__ void mma8(float* c, const uint32_t* a, const uint32_t* b) {
    asm volatile(
        "mma.sync.aligned.m16n8k8.row.col.f32.tf32.tf32.f32 "
        "{%0,%1,%2,%3},{%4,%5,%6,%7},{%8,%9},{%0,%1,%2,%3};"
        : "+f"(c[0]), "+f"(c[1]), "+f"(c[2]), "+f"(c[3])
        : "r"(a[0]), "r"(a[1]), "r"(a[2]), "r"(a[3]), "r"(b[0]), "r"(b[1]));
}

// ---------------- weight transpose + tf32 convert ----------------
__global__ void transpose_tf32_kernel(const float* __restrict__ src,
                                      float* __restrict__ dst, int R, int C, int do_zero) {
    __shared__ float tile[32][33];
    if (do_zero && blockIdx.x == 0 && blockIdx.y == 0 && blockIdx.z == 0 &&
        threadIdx.y == 0 && threadIdx.x < E_NUM)
        g_cnt[threadIdx.x] = 0;
    const int e = blockIdx.z;
    const int r0 = blockIdx.y * 32, c0 = blockIdx.x * 32;
    src += (size_t)e * R * C;
    dst += (size_t)e * R * C;
    const int tx = threadIdx.x, ty = threadIdx.y;
#pragma unroll
    for (int dy = 0; dy < 32; dy += 8)
        tile[ty + dy][tx] = src[(size_t)(r0 + ty + dy) * C + c0 + tx];
    __syncthreads();
#pragma unroll
    for (int dy = 0; dy < 32; dy += 8)
        dst[(size_t)(c0 + ty + dy) * R + r0 + tx] = __uint_as_float(f2tf(tile[tx][ty + dy]));
}

// ---------------- gate: logits, top-2, scatter ----------------
__global__ __launch_bounds__(512) void gate_kernel(
    const float* __restrict__ x, const float* __restrict__ gw,
    const float* __restrict__ gb)
{
    __shared__ float gws[E_NUM * D_DIM];
    const int tid = threadIdx.x;
    for (int i = tid; i < E_NUM * D_DIM; i += 512) {
        int e = i >> 10, d = i & 1023;
        gws[i] = gw[d * E_NUM + e];
    }
    __syncthreads();

    const int warp = tid >> 5, lane = tid & 31;
    const int tok0 = blockIdx.x * 64 + warp * 4;

    float acc[4][E_NUM];
#pragma unroll
    for (int t = 0; t < 4; t++)
#pragma unroll
        for (int e = 0; e < E_NUM; e++) acc[t][e] = 0.f;

    const float* xr = x + (size_t)tok0 * D_DIM;
    for (int d = lane; d < D_DIM; d += 32) {
        float xv[4];
#pragma unroll
        for (int t = 0; t < 4; t++) xv[t] = xr[(size_t)t * D_DIM + d];
#pragma unroll
        for (int e = 0; e < E_NUM; e++) {
            float w = gws[e * D_DIM + d];
#pragma unroll
            for (int t = 0; t < 4; t++) acc[t][e] += xv[t] * w;
        }
    }
#pragma unroll
    for (int t = 0; t < 4; t++)
#pragma unroll
        for (int e = 0; e < E_NUM; e++)
#pragma unroll
            for (int s = 16; s; s >>= 1)
                acc[t][e] += __shfl_xor_sync(0xffffffffu, acc[t][e], s);

    if (lane == 0) {
#pragma unroll
        for (int t = 0; t < 4; t++) {
            float l[E_NUM];
#pragma unroll
            for (int e = 0; e < E_NUM; e++) l[e] = acc[t][e] + gb[e];
            int i0 = 0;
#pragma unroll
            for (int e = 1; e < E_NUM; e++) if (l[e] > l[i0]) i0 = e;
            int i1 = (i0 == 0) ? 1 : 0;
#pragma unroll
            for (int e = 0; e < E_NUM; e++) if (e != i0 && l[e] > l[i1]) i1 = e;
            float e1 = expf(l[i1] - l[i0]);
            float s  = 1.0f + e1;
            int tok  = tok0 + t;
            int p0 = atomicAdd(&g_cnt[i0], 1);
            g_tok[i0][p0] = tok * 2 + 0; g_wgt[i0][p0] = 1.0f / s;
            int p1 = atomicAdd(&g_cnt[i1], 1);
            g_tok[i1][p1] = tok * 2 + 1; g_wgt[i1][p1] = e1 / s;
        }
    }
}

// ---------------- E1: h = gelu(x_tile[64,1024] @ w1^T + b1) -> g_h ----------------
__global__ void __launch_bounds__(NTHR, 2) expert1_kernel(
    const float* __restrict__ x, const float* __restrict__ b1)
{
    const int e     = blockIdx.y;
    const int cnt   = g_cnt[e];
    const int start = blockIdx.x * TM;
    if (start >= cnt) return;

    __shared__ int tids_s[TM];
    extern __shared__ __align__(16) char smem[];
    const uint32_t sb = smem_u32(smem);

    const int tid = threadIdx.x;
    if (tid < TM) {
        int src = (tid < cnt - start) ? (start + tid) : start;
        tids_s[tid] = g_tok[e][src] >> 1;   // token id
    }
    __syncthreads();

    const int warp = tid >> 5, lane = tid & 31;
    const int wm = warp & 1, wn = warp >> 1;         // 2(M,32) x 4(N,64)
    const int sub = lane >> 3, rin = lane & 7;
    const int g = lane >> 2, tg = lane & 3;
    const int arl = (sub & 1) * 8 + rin, auo = sub >> 1;
    const int brl = ((sub >> 1) & 1) * 8 + rin, buo = sub & 1;

    const float* w1e = g_w1t + (size_t)e * H_DIM * D_DIM;
    const float* b1e = b1 + e * H_DIM;

    auto load1 = [&](int slice, int st) {
        const int k0 = slice * 32;
        const uint32_t Ab = sb + st * ST_SZ;
        const uint32_t Bb = Ab + ST_A_SZ;
#pragma unroll
        for (int t = 0; t < 2; t++) {                 // A: 64x8 units, raw fp32
            int idx = tid + t * NTHR, r = idx >> 3, u = idx & 7;
            cp16(Ab + r * 128 + ((u ^ (r & 7)) << 4),
                 x + (size_t)tids_s[r] * D_DIM + k0 + u * 4);
        }
#pragma unroll
        for (int t = 0; t < 8; t++) {                 // B: 256x8 units, tf32
            int idx = tid + t * NTHR, r = idx >> 3, u = idx & 7;
            cp16(Bb + r * 128 + ((u ^ (r & 7)) << 4),
                 w1e + (size_t)r * D_DIM + k0 + u * 4);
        }
        cp_commit();
    };

    float c[2][8][4];
#pragma unroll
    for (int mi = 0; mi < 2; mi++)
#pragma unroll
        for (int ni = 0; ni < 8; ni++)
#pragma unroll
            for (int q = 0; q < 4; q++) c[mi][ni][q] = 0.f;

    load1(0, 0);
    for (int i = 0; i < 32; i++) {
        cp_wait<0>();
        __syncthreads();
        if (i + 1 < 32) load1(i + 1, (i + 1) & 1);
        const uint32_t Ab = sb + (i & 1) * ST_SZ;
        const uint32_t Bb = Ab + ST_A_SZ;
#pragma unroll
        for (int kk = 0; kk < 4; kk++) {
            uint32_t a[2][4], bf[4][4];
#pragma unroll
            for (int mi = 0; mi < 2; mi++) {
                int row = wm * 32 + mi * 16 + arl;
                int u   = 2 * kk + auo;
                ldsm4(a[mi], Ab + row * 128 + ((u ^ (row & 7)) << 4));
#pragma unroll
                for (int q = 0; q < 4; q++)           // raw fp32 -> tf32 (RNA)
                    a[mi][q] = f2tf(__uint_as_float(a[mi][q]));
            }
#pragma unroll
            for (int p = 0; p < 4; p++) {
                int row = wn * 64 + p * 16 + brl;
                int u   = 2 * kk + buo;
                ldsm4(bf[p], Bb + row * 128 + ((u ^ (row & 7)) << 4));
            }
#pragma unroll
            for (int mi = 0; mi < 2; mi++)
#pragma unroll
                for (int ni = 0; ni < 8; ni++)
                    mma8(c[mi][ni], a[mi], &bf[ni >> 1][(ni & 1) * 2]);
        }
    }
    __syncthreads();   // ring dead; reuse as h staging [64][264]

    // bias + exact gelu -> staging (tf32 bits)
#pragma unroll
    for (int mi = 0; mi < 2; mi++) {
#pragma unroll
        for (int ni = 0; ni < 8; ni++) {
            int col = wn * 64 + ni * 8 + tg * 2;
            float bb0 = b1e[col], bb1 = b1e[col + 1];
#pragma unroll
            for (int h = 0; h < 2; h++) {
                int row = wm * 32 + mi * 16 + g + h * 8;
                float v0 = c[mi][ni][h * 2]     + bb0;
                float v1 = c[mi][ni][h * 2 + 1] + bb1;
                v0 = 0.5f * v0 * (1.0f + erff(v0 * 0.70710678f));
                v1 = 0.5f * v1 * (1.0f + erff(v1 * 0.70710678f));
                uint32_t addr = sb + (row * 264 + col) * 4;
                asm volatile("st.shared.v2.b32 [%0],{%1,%2};"
                             :: "r"(addr), "r"(f2tf(v0)), "r"(f2tf(v1)));
            }
        }
    }
    __syncthreads();

    // coalesced copy staging -> g_h[e][start..start+64)
    float* hdst = g_h + ((size_t)e * B_TOK + start) * H_DIM;
#pragma unroll
    for (int t = 0; t < 16; t++) {
        int ch = tid + t * NTHR;                      // 4096 uint4
        int row = ch >> 6, c4 = ch & 63;
        uint4 v;
        asm volatile("ld.shared.v4.b32 {%0,%1,%2,%3},[%4];"
                     : "=r"(v.x), "=r"(v.y), "=r"(v.z), "=r"(v.w)
                     : "r"(sb + (row * 264 + c4 * 4) * 4));
        *(uint4*)(hdst + (size_t)row * H_DIM + c4 * 4) = v;
    }
}

// ---------------- E2: out_panel = h[64,256] @ w2^T panel -> weighted partials ----------------
__global__ void __launch_bounds__(NTHR, 2) expert2_kernel(
    const float* __restrict__ b2)
{
    const int e     = blockIdx.z;
    const int py    = blockIdx.y;                    // N panel (256 cols of 1024)
    const int cnt   = g_cnt[e];
    const int start = blockIdx.x * TM;
    if (start >= cnt) return;
    const int mcount = min(TM, cnt - start);

    __shared__ int   tids_s[TM];
    __shared__ float wts_s[TM];
    extern __shared__ __align__(16) char smem[];
    const uint32_t sb = smem_u32(smem);

    const int tid = threadIdx.x;
    if (tid < TM) {
        bool v = tid < mcount;
        int  src = v ? (start + tid) : start;
        tids_s[tid] = g_tok[e][src];
        wts_s[tid]  = v ? g_wgt[e][src] : 0.f;
    }
    __syncthreads();

    const int warp = tid >> 5, lane = tid & 31;
    const int wm = warp & 1, wn = warp >> 1;
    const int sub = lane >> 3, rin = lane & 7;
    const int g = lane >> 2, tg = lane & 3;
    const int arl = (sub & 1) * 8 + rin, auo = sub >> 1;
    const int brl = ((sub >> 1) & 1) * 8 + rin, buo = sub & 1;

    const float* hsrc = g_h + ((size_t)e * B_TOK + start) * H_DIM;
    const float* w2e  = g_w2t + (size_t)e * D_DIM * H_DIM + (size_t)py * 256 * H_DIM;
    const float* b2e  = b2 + e * D_DIM + py * 256;

    auto load2 = [&](int slice, int st) {
        const int k0 = slice * 32;
        const uint32_t Ab = sb + st * ST_SZ;
        const uint32_t Bb = Ab + ST_A_SZ;
#pragma unroll
        for (int t = 0; t < 2; t++) {                 // A: h rows, already tf32
            int idx = tid + t * NTHR, r = idx >> 3, u = idx & 7;
            cp16(Ab + r * 128 + ((u ^ (r & 7)) << 4),
                 hsrc + (size_t)r * H_DIM + k0 + u * 4);
        }
#pragma unroll
        for (int t = 0; t < 8; t++) {                 // B: w2 panel rows
            int idx = tid + t * NTHR, r = idx >> 3, u = idx & 7;
            cp16(Bb + r * 128 + ((u ^ (r & 7)) << 4),
                 w2e + (size_t)r * H_DIM + k0 + u * 4);
        }
        cp_commit();
    };

    float c[2][8][4];
#pragma unroll
    for (int mi = 0; mi < 2; mi++)
#pragma unroll
        for (int ni = 0; ni < 8; ni++)
#pragma unroll
            for (int q = 0; q < 4; q++) c[mi][ni][q] = 0.f;

    load2(0, 0);
    for (int i = 0; i < 8; i++) {
        cp_wait<0>();
        __syncthreads();
        if (i + 1 < 8) load2(i + 1, (i + 1) & 1);
        const uint32_t Ab = sb + (i & 1) * ST_SZ;
        const uint32_t Bb = Ab + ST_A_SZ;
#pragma unroll
        for (int kk = 0; kk < 4; kk++) {
            uint32_t a[2][4], bf[4][4];
#pragma unroll
            for (int mi = 0; mi < 2; mi++) {
                int row = wm * 32 + mi * 16 + arl;
                int u   = 2 * kk + auo;
                ldsm4(a[mi], Ab + row * 128 + ((u ^ (row & 7)) << 4));
            }
#pragma unroll
            for (int p = 0; p < 4; p++) {
                int row = wn * 64 + p * 16 + brl;
                int u   = 2 * kk + buo;
                ldsm4(bf[p], Bb + row * 128 + ((u ^ (row & 7)) << 4));
            }
#pragma unroll
            for (int mi = 0; mi < 2; mi++)
#pragma unroll
                for (int ni = 0; ni < 8; ni++)
                    mma8(c[mi][ni], a[mi], &bf[ni >> 1][(ni & 1) * 2]);
        }
    }

    // weighted partial store (no atomics; rank plane per token)
#pragma unroll
    for (int mi = 0; mi < 2; mi++) {
#pragma unroll
        for (int h = 0; h < 2; h++) {
            int r = wm * 32 + mi * 16 + g + h * 8;
            if (r < mcount) {
                int   raw = tids_s[r];
                float wt  = wts_s[r];
                float* dst = g_part + (size_t)(raw & 1) * ((size_t)B_TOK * D_DIM)
                           + (size_t)(raw >> 1) * D_DIM + py * 256;
#pragma unroll
                for (int ni = 0; ni < 8; ni++) {
                    int col = wn * 64 + ni * 8 + tg * 2;
                    float v0 = (c[mi][ni][h * 2]     + b2e[col])     * wt;
                    float v1 = (c[mi][ni][h * 2 + 1] + b2e[col + 1]) * wt;
                    *(float2*)(dst + col) = make_float2(v0, v1);
                }
            }
        }
    }
}

// ---------------- combine: out = part0 + part1 ----------------
__global__ __launch_bounds__(256) void combine_kernel(float* __restrict__ out) {
    size_t i = ((size_t)blockIdx.x * 256 + threadIdx.x) * 4;
    float4 a = *(const float4*)(g_part + i);
    float4 b = *(const float4*)(g_part + (size_t)B_TOK * D_DIM + i);
    *(float4*)(out + i) = make_float4(a.x + b.x, a.y + b.y, a.z + b.z, a.w + b.w);
}

// ---------------- launch ----------------
extern "C" void kernel_launch(void* const* d_in, const int* in_sizes, int n_in,
                              void* d_out, int out_size) {
    const float* x  = (const float*)d_in[0];
    const float* gw = (const float*)d_in[1];
    const float* gb = (const float*)d_in[2];
    const float* w1 = (const float*)d_in[3];
    const float* b1 = (const float*)d_in[4];
    const float* w2 = (const float*)d_in[5];
    const float* b2 = (const float*)d_in[6];
    float* out = (float*)d_out;

    static float* w1t_ptr = nullptr;
    static float* w2t_ptr = nullptr;
    if (!w1t_ptr) {
        cudaGetSymbolAddress((void**)&w1t_ptr, g_w1t);
        cudaGetSymbolAddress((void**)&w2t_ptr, g_w2t);
        cudaFuncSetAttribute(expert1_kernel,
                             cudaFuncAttributeMaxDynamicSharedMemorySize, DYN_SMEM);
        cudaFuncSetAttribute(expert2_kernel,
                             cudaFuncAttributeMaxDynamicSharedMemorySize, DYN_SMEM);
    }

    transpose_tf32_kernel<<<dim3(H_DIM / 32, D_DIM / 32, E_NUM), dim3(32, 8)>>>(
        w1, w1t_ptr, D_DIM, H_DIM, 1);
    transpose_tf32_kernel<<<dim3(D_DIM / 32, H_DIM / 32, E_NUM), dim3(32, 8)>>>(
        w2, w2t_ptr, H_DIM, D_DIM, 0);
    gate_kernel<<<B_TOK / 64, 512>>>(x, gw, gb);
    expert1_kernel<<<dim3(B_TOK / TM, E_NUM), NTHR, DYN_SMEM>>>(x, b1);
    expert2_kernel<<<dim3(B_TOK / TM, 4, E_NUM), NTHR, DYN_SMEM>>>(b2);
    combine_kernel<<<B_TOK * D_DIM / 1024, 256>>>(out);
}

// round 7
// speedup vs baseline: 1.0013x; 1.0013x over previous
#include <cuda_runtime.h>
#include <math.h>
#include <stdint.h>

#define B_TOK 16384
#define D_DIM 1024
#define H_DIM 256
#define E_NUM 8
#define TM    64
#define NTHR  256

// 2-stage ring: stage = A(64x128B = 8KB) @0 + B(256x128B = 32KB) @8192 = 40KB
#define ST_SZ   40960
#define ST_B    8192
#define DYN_SMEM 81920

// ---------------- device scratch ----------------
__device__ int   g_cnt[E_NUM];
__device__ int   g_tok[E_NUM][B_TOK];          // tok*2 + rank
__device__ float g_wgt[E_NUM][B_TOK];
// tiled + pre-swizzled weights: [e][slice][n][32] tf32, 32KB per (e,slice,256-n-chunk)
__device__ float g_w1t[(size_t)E_NUM * H_DIM * D_DIM];
__device__ float g_w2t[(size_t)E_NUM * D_DIM * H_DIM];
__device__ float g_h[(size_t)E_NUM * B_TOK * H_DIM];     // gelu(h) tf32, [e][pos][256]
__device__ float g_part[2ull * B_TOK * D_DIM];           // rank partials

// ---------------- helpers ----------------
__device__ __forceinline__ uint32_t smem_u32(const void* p) {
    uint32_t r;
    asm("{.reg .u64 t; cvta.to.shared.u64 t,%1; cvt.u32.u64 %0,t;}" : "=r"(r) : "l"(p));
    return r;
}
__device__ __forceinline__ uint32_t f2tf(float f) {
    uint32_t u; asm("cvt.rna.tf32.f32 %0,%1;" : "=r"(u) : "f"(f)); return u;
}
__device__ __forceinline__ void cp16(uint32_t s, const void* g) {
    asm volatile("cp.async.cg.shared.global [%0],[%1],16;" :: "r"(s), "l"(g));
}
__device__ __forceinline__ void cp_commit() {
    asm volatile("cp.async.commit_group;" ::: "memory");
}
template <int N> __device__ __forceinline__ void cp_wait() {
    asm volatile("cp.async.wait_group %0;" :: "n"(N) : "memory");
}
__device__ __forceinline__ void mbar_init(uint32_t mb, uint32_t cnt) {
    asm volatile("mbarrier.init.shared.b64 [%0], %1;" :: "r"(mb), "r"(cnt) : "memory");
}
__device__ __forceinline__ void mbar_expect(uint32_t mb, uint32_t bytes) {
    asm volatile("mbarrier.arrive.expect_tx.shared.b64 _, [%0], %1;"
                 :: "r"(mb), "r"(bytes) : "memory");
}
__device__ __forceinline__ void bulk_g2s(uint32_t dst, const void* src,
                                         uint32_t bytes, uint32_t mb) {
    asm volatile(
        "cp.async.bulk.shared::cluster.global.mbarrier::complete_tx::bytes "
        "[%0], [%1], %2, [%3];"
        :: "r"(dst), "l"(src), "r"(bytes), "r"(mb) : "memory");
}
__device__ __forceinline__ void mbar_wait(uint32_t mb, uint32_t ph) {
    asm volatile(
        "{.reg .pred P;\n\t"
        "WL%=:\n\t"
        "mbarrier.try_wait.parity.acquire.cta.shared::cta.b64 P,[%0],%1,0x989680;\n\t"
        "@P bra WD%=;\n\t"
        "bra WL%=;\n\t"
        "WD%=:}" :: "r"(mb), "r"(ph) : "memory");
}
__device__ __forceinline__ void ldsm4(uint32_t* r, uint32_t a) {
    asm volatile("ldmatrix.sync.aligned.m8n8.x4.shared.b16 {%0,%1,%2,%3},[%4];"
                 : "=r"(r[0]), "=r"(r[1]), "=r"(r[2]), "=r"(r[3]) : "r"(a));
}
__device__ __forceinline__ void mma8(float* c, const uint32_t* a, const uint32_t* b) {
    asm volatile(
        "mma.sync.aligned.m16n8k8.row.col.f32.tf32.tf32.f32 "
        "{%0,%1,%2,%3},{%4,%5,%6,%7},{%8,%9},{%0,%1,%2,%3};"
        : "+f"(c[0]), "+f"(c[1]), "+f"(c[2]), "+f"(c[3])
        : "r"(a[0]), "r"(a[1]), "r"(a[2]), "r"(a[3]), "r"(b[0]), "r"(b[1]));
}

// ---------------- weight prep: transpose + tf32 + tile + swizzle ----------------
// src [E][K][N] fp32 -> dst[((e*(K/32)+s)*N + n)*32 + ((c>>2 ^ (n&7))*4 + (c&3))]
//   = tf32(src[e][s*32+c][n]).  One block per (n0 32-chunk, s, e).
__global__ void prep_w_kernel(const float* __restrict__ src, float* __restrict__ dst,
                              int K, int N, int do_zero) {
    __shared__ float tile[32][33];
    if (do_zero && blockIdx.x == 0 && blockIdx.y == 0 && blockIdx.z == 0 &&
        threadIdx.y == 0 && threadIdx.x < E_NUM)
        g_cnt[threadIdx.x] = 0;
    const int e = blockIdx.z;
    const int s = blockIdx.y;            // K-slice
    const int n0 = blockIdx.x * 32;
    const int tx = threadIdx.x, ty = threadIdx.y;
    const float* sp = src + (size_t)e * K * N + (size_t)s * 32 * N + n0;
#pragma unroll
    for (int dy = 0; dy < 32; dy += 8)                   // read rows k, coalesced over n
        tile[ty + dy][tx] = sp[(size_t)(ty + dy) * N + tx];
    __syncthreads();
    float* dp = dst + (((size_t)e * (K / 32) + s) * N + n0) * 32;
#pragma unroll
    for (int dy = 0; dy < 32; dy += 8) {
        int n = ty + dy;                                  // local n row
        int c = tx;                                       // k within slice
        dp[(size_t)n * 32 + (((c >> 2) ^ ((n0 + n) & 7)) * 4 + (c & 3))] =
            __uint_as_float(f2tf(tile[c][n]));
    }
}

// ---------------- gate: logits, top-2, scatter ----------------
__global__ __launch_bounds__(512) void gate_kernel(
    const float* __restrict__ x, const float* __restrict__ gw,
    const float* __restrict__ gb)
{
    __shared__ float gws[E_NUM * D_DIM];
    const int tid = threadIdx.x;
    for (int i = tid; i < E_NUM * D_DIM; i += 512) {
        int e = i >> 10, d = i & 1023;
        gws[i] = gw[d * E_NUM + e];
    }
    __syncthreads();

    const int warp = tid >> 5, lane = tid & 31;
    const int tok0 = blockIdx.x * 64 + warp * 4;

    float acc[4][E_NUM];
#pragma unroll
    for (int t = 0; t < 4; t++)
#pragma unroll
        for (int e = 0; e < E_NUM; e++) acc[t][e] = 0.f;

    const float* xr = x + (size_t)tok0 * D_DIM;
    for (int d = lane; d < D_DIM; d += 32) {
        float xv[4];
#pragma unroll
        for (int t = 0; t < 4; t++) xv[t] = xr[(size_t)t * D_DIM + d];
#pragma unroll
        for (int e = 0; e < E_NUM; e++) {
            float w = gws[e * D_DIM + d];
#pragma unroll
            for (int t = 0; t < 4; t++) acc[t][e] += xv[t] * w;
        }
    }
#pragma unroll
    for (int t = 0; t < 4; t++)
#pragma unroll
        for (int e = 0; e < E_NUM; e++)
#pragma unroll
            for (int s = 16; s; s >>= 1)
                acc[t][e] += __shfl_xor_sync(0xffffffffu, acc[t][e], s);

    if (lane == 0) {
#pragma unroll
        for (int t = 0; t < 4; t++) {
            float l[E_NUM];
#pragma unroll
            for (int e = 0; e < E_NUM; e++) l[e] = acc[t][e] + gb[e];
            int i0 = 0;
#pragma unroll
            for (int e = 1; e < E_NUM; e++) if (l[e] > l[i0]) i0 = e;
            int i1 = (i0 == 0) ? 1 : 0;
#pragma unroll
            for (int e = 0; e < E_NUM; e++) if (e != i0 && l[e] > l[i1]) i1 = e;
            float e1 = expf(l[i1] - l[i0]);
            float s  = 1.0f + e1;
            int tok  = tok0 + t;
            int p0 = atomicAdd(&g_cnt[i0], 1);
            g_tok[i0][p0] = tok * 2 + 0; g_wgt[i0][p0] = 1.0f / s;
            int p1 = atomicAdd(&g_cnt[i1], 1);
            g_tok[i1][p1] = tok * 2 + 1; g_wgt[i1][p1] = e1 / s;
        }
    }
}

// ---------------- E1: h = gelu(x[64,1024] @ w1^T + b1) -> g_h ----------------
__global__ void __launch_bounds__(NTHR, 2) expert1_kernel(
    const float* __restrict__ x, const float* __restrict__ b1)
{
    const int e     = blockIdx.y;
    const int cnt   = g_cnt[e];
    const int start = blockIdx.x * TM;
    if (start >= cnt) return;

    __shared__ int tids_s[TM];
    __shared__ __align__(8) uint64_t mbar_s[2];
    extern __shared__ __align__(16) char smem[];
    const uint32_t sb = smem_u32(smem);

    const int tid = threadIdx.x;
    if (tid < TM) {
        int src = (tid < cnt - start) ? (start + tid) : start;
        tids_s[tid] = g_tok[e][src] >> 1;
    }
    const uint32_t mb[2] = { smem_u32(&mbar_s[0]), smem_u32(&mbar_s[1]) };
    if (tid == 0) { mbar_init(mb[0], 1); mbar_init(mb[1], 1); }
    __syncthreads();

    const int warp = tid >> 5, lane = tid & 31;
    const int wm = warp & 1, wn = warp >> 1;
    const int sub = lane >> 3, rin = lane & 7;
    const int g = lane >> 2, tg = lane & 3;
    const int arl = (sub & 1) * 8 + rin, auo = sub >> 1;
    const int brl = ((sub >> 1) & 1) * 8 + rin, buo = sub & 1;

    const float* w1t = g_w1t + (size_t)e * 32 * 8192;    // [slice][32KB]
    const float* b1e = b1 + e * H_DIM;

    // per-thread A-gather pointers (loop-invariant rows, advance by 32 floats/slice)
    const int r0 = tid >> 2, u0 = tid & 3;               // rows 0..63, units 0..3
    const int r1 = r0,       u1 = u0 + 4;                // units 4..7
    const float* ga0 = x + (size_t)tids_s[r0] * D_DIM + u0 * 4;
    const float* ga1 = x + (size_t)tids_s[r1] * D_DIM + u1 * 4;
    const uint32_t sa0 = r0 * 128 + ((u0 ^ (r0 & 7)) << 4);
    const uint32_t sa1 = r1 * 128 + ((u1 ^ (r1 & 7)) << 4);

    float c[2][8][4];
#pragma unroll
    for (int mi = 0; mi < 2; mi++)
#pragma unroll
        for (int ni = 0; ni < 8; ni++)
#pragma unroll
            for (int q = 0; q < 4; q++) c[mi][ni][q] = 0.f;

    int ph[2] = {0, 0};

    // prologue: slice 0 -> buf 0
    if (tid == 0) { mbar_expect(mb[0], 32768); bulk_g2s(sb + ST_B, w1t, 32768, mb[0]); }
    cp16(sb + sa0, ga0); cp16(sb + sa1, ga1); cp_commit();

    for (int i = 0; i < 32; i++) {
        const int b = i & 1;
        cp_wait<0>();
        mbar_wait(mb[b], ph[b]); ph[b] ^= 1;
        __syncthreads();
        if (i + 1 < 32) {
            const int nb = b ^ 1;
            const uint32_t st = sb + nb * ST_SZ;
            if (tid == 0) {
                mbar_expect(mb[nb], 32768);
                bulk_g2s(st + ST_B, w1t + (size_t)(i + 1) * 8192, 32768, mb[nb]);
            }
            cp16(st + sa0, ga0 + (i + 1) * 32);
            cp16(st + sa1, ga1 + (i + 1) * 32);
            cp_commit();
        }
        const uint32_t Ab = sb + b * ST_SZ;
        const uint32_t Bb = Ab + ST_B;
#pragma unroll
        for (int kk = 0; kk < 4; kk++) {
            uint32_t a[2][4], bf[4][4];
#pragma unroll
            for (int mi = 0; mi < 2; mi++) {
                int row = wm * 32 + mi * 16 + arl;
                int u   = 2 * kk + auo;
                ldsm4(a[mi], Ab + row * 128 + ((u ^ (row & 7)) << 4));
#pragma unroll
                for (int q = 0; q < 4; q++)
                    a[mi][q] = f2tf(__uint_as_float(a[mi][q]));
            }
#pragma unroll
            for (int p = 0; p < 4; p++) {
                int row = wn * 64 + p * 16 + brl;
                int u   = 2 * kk + buo;
                ldsm4(bf[p], Bb + row * 128 + ((u ^ (row & 7)) << 4));
            }
#pragma unroll
            for (int mi = 0; mi < 2; mi++)
#pragma unroll
                for (int ni = 0; ni < 8; ni++)
                    mma8(c[mi][ni], a[mi], &bf[ni >> 1][(ni & 1) * 2]);
        }
    }
    __syncthreads();   // buffers dead; reuse smem as h staging [64][264]

    // bias + exact gelu -> staging (tf32 bits)
#pragma unroll
    for (int mi = 0; mi < 2; mi++) {
#pragma unroll
        for (int ni = 0; ni < 8; ni++) {
            int col = wn * 64 + ni * 8 + tg * 2;
            float bb0 = b1e[col], bb1 = b1e[col + 1];
#pragma unroll
            for (int h = 0; h < 2; h++) {
                int row = wm * 32 + mi * 16 + g + h * 8;
                float v0 = c[mi][ni][h * 2]     + bb0;
                float v1 = c[mi][ni][h * 2 + 1] + bb1;
                v0 = 0.5f * v0 * (1.0f + erff(v0 * 0.70710678f));
                v1 = 0.5f * v1 * (1.0f + erff(v1 * 0.70710678f));
                uint32_t addr = sb + (row * 264 + col) * 4;
                asm volatile("st.shared.v2.b32 [%0],{%1,%2};"
                             :: "r"(addr), "r"(f2tf(v0)), "r"(f2tf(v1)));
            }
        }
    }
    __syncthreads();

    float* hdst = g_h + ((size_t)e * B_TOK + start) * H_DIM;
#pragma unroll
    for (int t = 0; t < 16; t++) {
        int ch = tid + t * NTHR;
        int row = ch >> 6, c4 = ch & 63;
        uint4 v;
        asm volatile("ld.shared.v4.b32 {%0,%1,%2,%3},[%4];"
                     : "=r"(v.x), "=r"(v.y), "=r"(v.z), "=r"(v.w)
                     : "r"(sb + (row * 264 + c4 * 4) * 4));
        *(uint4*)(hdst + (size_t)row * H_DIM + c4 * 4) = v;
    }
}

// ---------------- E2: out_panel = h[64,256] @ w2^T panel -> weighted partials ----------------
__global__ void __launch_bounds__(NTHR, 2) expert2_kernel(
    const float* __restrict__ b2)
{
    const int e     = blockIdx.z;
    const int py    = blockIdx.y;
    const int cnt   = g_cnt[e];
    const int start = blockIdx.x * TM;
    if (start >= cnt) return;
    const int mcount = min(TM, cnt - start);

    __shared__ int   tids_s[TM];
    __shared__ float wts_s[TM];
    __shared__ __align__(8) uint64_t mbar_s[2];
    extern __shared__ __align__(16) char smem[];
    const uint32_t sb = smem_u32(smem);

    const int tid = threadIdx.x;
    if (tid < TM) {
        bool v = tid < mcount;
        int  src = v ? (start + tid) : start;
        tids_s[tid] = g_tok[e][src];
        wts_s[tid]  = v ? g_wgt[e][src] : 0.f;
    }
    const uint32_t mb[2] = { smem_u32(&mbar_s[0]), smem_u32(&mbar_s[1]) };
    if (tid == 0) { mbar_init(mb[0], 1); mbar_init(mb[1], 1); }
    __syncthreads();

    const int warp = tid >> 5, lane = tid & 31;
    const int wm = warp & 1, wn = warp >> 1;
    const int sub = lane >> 3, rin = lane & 7;
    const int g = lane >> 2, tg = lane & 3;
    const int arl = (sub & 1) * 8 + rin, auo = sub >> 1;
    const int brl = ((sub >> 1) & 1) * 8 + rin, buo = sub & 1;

    // B source: [e][s(8)][n(1024)][32]; panel chunk = 256 rows from py*256
    const float* w2t = g_w2t + (size_t)e * 8 * 1024 * 32 + (size_t)py * 256 * 32;
    const float* b2e = b2 + e * D_DIM + py * 256;

    const int r0 = tid >> 2, u0 = tid & 3;
    const float* ha0 = g_h + ((size_t)e * B_TOK + start + r0) * H_DIM + u0 * 4;
    const float* ha1 = ha0 + 16;
    const int u1 = u0 + 4;
    const uint32_t sa0 = r0 * 128 + ((u0 ^ (r0 & 7)) << 4);
    const uint32_t sa1 = r0 * 128 + ((u1 ^ (r0 & 7)) << 4);

    float c[2][8][4];
#pragma unroll
    for (int mi = 0; mi < 2; mi++)
#pragma unroll
        for (int ni = 0; ni < 8; ni++)
#pragma unroll
            for (int q = 0; q < 4; q++) c[mi][ni][q] = 0.f;

    int ph[2] = {0, 0};

    if (tid == 0) { mbar_expect(mb[0], 32768); bulk_g2s(sb + ST_B, w2t, 32768, mb[0]); }
    cp16(sb + sa0, ha0); cp16(sb + sa1, ha1); cp_commit();

    for (int i = 0; i < 8; i++) {
        const int b = i & 1;
        cp_wait<0>();
        mbar_wait(mb[b], ph[b]); ph[b] ^= 1;
        __syncthreads();
        if (i + 1 < 8) {
            const int nb = b ^ 1;
            const uint32_t st = sb + nb * ST_SZ;
            if (tid == 0) {
                mbar_expect(mb[nb], 32768);
                bulk_g2s(st + ST_B, w2t + (size_t)(i + 1) * 1024 * 32, 32768, mb[nb]);
            }
            cp16(st + sa0, ha0 + (i + 1) * 32);
            cp16(st + sa1, ha1 + (i + 1) * 32);
            cp_commit();
        }
        const uint32_t Ab = sb + b * ST_SZ;
        const uint32_t Bb = Ab + ST_B;
#pragma unroll
        for (int kk = 0; kk < 4; kk++) {
            uint32_t a[2][4], bf[4][4];
#pragma unroll
            for (int mi = 0; mi < 2; mi++) {
                int row = wm * 32 + mi * 16 + arl;
                int u   = 2 * kk + auo;
                ldsm4(a[mi], Ab + row * 128 + ((u ^ (row & 7)) << 4));
            }
#pragma unroll
            for (int p = 0; p < 4; p++) {
                int row = wn * 64 + p * 16 + brl;
                int u   = 2 * kk + buo;
                ldsm4(bf[p], Bb + row * 128 + ((u ^ (row & 7)) << 4));
            }
#pragma unroll
            for (int mi = 0; mi < 2; mi++)
#pragma unroll
                for (int ni = 0; ni < 8; ni++)
                    mma8(c[mi][ni], a[mi], &bf[ni >> 1][(ni & 1) * 2]);
        }
    }

    // weighted partial store (no atomics; rank plane per token)
#pragma unroll
    for (int mi = 0; mi < 2; mi++) {
#pragma unroll
        for (int h = 0; h < 2; h++) {
            int r = wm * 32 + mi * 16 + g + h * 8;
            if (r < mcount) {
                int   raw = tids_s[r];
                float wt  = wts_s[r];
                float* dst = g_part + (size_t)(raw & 1) * ((size_t)B_TOK * D_DIM)
                           + (size_t)(raw >> 1) * D_DIM + py * 256;
#pragma unroll
                for (int ni = 0; ni < 8; ni++) {
                    int col = wn * 64 + ni * 8 + tg * 2;
                    float v0 = (c[mi][ni][h * 2]     + b2e[col])     * wt;
                    float v1 = (c[mi][ni][h * 2 + 1] + b2e[col + 1]) * wt;
                    *(float2*)(dst + col) = make_float2(v0, v1);
                }
            }
        }
    }
}

// ---------------- combine: out = part0 + part1 ----------------
__global__ __launch_bounds__(256) void combine_kernel(float* __restrict__ out) {
    size_t i = ((size_t)blockIdx.x * 256 + threadIdx.x) * 4;
    float4 a = *(const float4*)(g_part + i);
    float4 b = *(const float4*)(g_part + (size_t)B_TOK * D_DIM + i);
    *(float4*)(out + i) = make_float4(a.x + b.x, a.y + b.y, a.z + b.z, a.w + b.w);
}

// ---------------- launch ----------------
extern "C" void kernel_launch(void* const* d_in, const int* in_sizes, int n_in,
                              void* d_out, int out_size) {
    const float* x  = (const float*)d_in[0];
    const float* gw = (const float*)d_in[1];
    const float* gb = (const float*)d_in[2];
    const float* w1 = (const float*)d_in[3];
    const float* b1 = (const float*)d_in[4];
    const float* w2 = (const float*)d_in[5];
    const float* b2 = (const float*)d_in[6];
    float* out = (float*)d_out;

    static float* w1t_ptr = nullptr;
    static float* w2t_ptr = nullptr;
    if (!w1t_ptr) {
        cudaGetSymbolAddress((void**)&w1t_ptr, g_w1t);
        cudaGetSymbolAddress((void**)&w2t_ptr, g_w2t);
        cudaFuncSetAttribute(expert1_kernel,
                             cudaFuncAttributeMaxDynamicSharedMemorySize, DYN_SMEM);
        cudaFuncSetAttribute(expert2_kernel,
                             cudaFuncAttributeMaxDynamicSharedMemorySize, DYN_SMEM);
    }

    // w1 [e][D][H]: K=D, N=H ; w2 [e][H][D]: K=H, N=D
    prep_w_kernel<<<dim3(H_DIM / 32, D_DIM / 32, E_NUM), dim3(32, 8)>>>(
        w1, w1t_ptr, D_DIM, H_DIM, 1);
    prep_w_kernel<<<dim3(D_DIM / 32, H_DIM / 32, E_NUM), dim3(32, 8)>>>(
        w2, w2t_ptr, H_DIM, D_DIM, 0);
    gate_kernel<<<B_TOK / 64, 512>>>(x, gw, gb);
    expert1_kernel<<<dim3(B_TOK / TM, E_NUM), NTHR, DYN_SMEM>>>(x, b1);
    expert2_kernel<<<dim3(B_TOK / TM, 4, E_NUM), NTHR, DYN_SMEM>>>(b2);
    combine_kernel<<<B_TOK * D_DIM / 1024, 256>>>(out);
}

// round 8
// speedup vs baseline: 1.3775x; 1.3757x over previous
#include <cuda_runtime.h>
#include <cuda_fp16.h>
#include <math.h>
#include <stdint.h>

#define B_TOK 16384
#define D_DIM 1024
#define H_DIM 256
#define E_NUM 8
#define TM    64
#define NTHR  256

// 2-stage ring: stage = A(64 rows x 128B = 8KB) @0 + B(256 rows x 128B = 32KB) @8192
#define ST_SZ   40960
#define ST_B    8192
#define DYN_SMEM 81920

// ---------------- device scratch ----------------
__device__ int    g_cnt[E_NUM];
__device__ int    g_tok[E_NUM][B_TOK];          // tok*2 + rank
__device__ float  g_wgt[E_NUM][B_TOK];
__device__ __half g_xh[(size_t)B_TOK * D_DIM];                 // x fp16
// tiled + pre-swizzled fp16 weights: [e][slice(k64)][n][64 halves swizzled]
__device__ __half g_w1h[(size_t)E_NUM * H_DIM * D_DIM];
__device__ __half g_w2h[(size_t)E_NUM * D_DIM * H_DIM];
__device__ __half g_h[(size_t)E_NUM * B_TOK * H_DIM];          // gelu(h) fp16

// ---------------- helpers ----------------
__device__ __forceinline__ uint32_t smem_u32(const void* p) {
    uint32_t r;
    asm("{.reg .u64 t; cvta.to.shared.u64 t,%1; cvt.u32.u64 %0,t;}" : "=r"(r) : "l"(p));
    return r;
}
__device__ __forceinline__ void cp16(uint32_t s, const void* g) {
    asm volatile("cp.async.cg.shared.global [%0],[%1],16;" :: "r"(s), "l"(g));
}
__device__ __forceinline__ void cp_commit() {
    asm volatile("cp.async.commit_group;" ::: "memory");
}
template <int N> __device__ __forceinline__ void cp_wait() {
    asm volatile("cp.async.wait_group %0;" :: "n"(N) : "memory");
}
__device__ __forceinline__ void mbar_init(uint32_t mb, uint32_t cnt) {
    asm volatile("mbarrier.init.shared.b64 [%0], %1;" :: "r"(mb), "r"(cnt) : "memory");
}
__device__ __forceinline__ void mbar_expect(uint32_t mb, uint32_t bytes) {
    asm volatile("mbarrier.arrive.expect_tx.shared.b64 _, [%0], %1;"
                 :: "r"(mb), "r"(bytes) : "memory");
}
__device__ __forceinline__ void bulk_g2s(uint32_t dst, const void* src,
                                         uint32_t bytes, uint32_t mb) {
    asm volatile(
        "cp.async.bulk.shared::cluster.global.mbarrier::complete_tx::bytes "
        "[%0], [%1], %2, [%3];"
        :: "r"(dst), "l"(src), "r"(bytes), "r"(mb) : "memory");
}
__device__ __forceinline__ void mbar_wait(uint32_t mb, uint32_t ph) {
    asm volatile(
        "{.reg .pred P;\n\t"
        "WL%=:\n\t"
        "mbarrier.try_wait.parity.acquire.cta.shared::cta.b64 P,[%0],%1,0x989680;\n\t"
        "@P bra WD%=;\n\t"
        "bra WL%=;\n\t"
        "WD%=:}" :: "r"(mb), "r"(ph) : "memory");
}
__device__ __forceinline__ void ldsm4(uint32_t* r, uint32_t a) {
    asm volatile("ldmatrix.sync.aligned.m8n8.x4.shared.b16 {%0,%1,%2,%3},[%4];"
                 : "=r"(r[0]), "=r"(r[1]), "=r"(r[2]), "=r"(r[3]) : "r"(a));
}
// m16n8k16 fp16 mma, fp32 accum
__device__ __forceinline__ void mma16(float* c, const uint32_t* a, const uint32_t* b) {
    asm volatile(
        "mma.sync.aligned.m16n8k16.row.col.f32.f16.f16.f32 "
        "{%0,%1,%2,%3},{%4,%5,%6,%7},{%8,%9},{%0,%1,%2,%3};"
        : "+f"(c[0]), "+f"(c[1]), "+f"(c[2]), "+f"(c[3])
        : "r"(a[0]), "r"(a[1]), "r"(a[2]), "r"(a[3]), "r"(b[0]), "r"(b[1]));
}

// ---------------- weight prep: [E][K][N] fp32 -> [e][k/64][n][64] fp16 swizzled ----------------
__global__ void prep_w_kernel(const float* __restrict__ src, __half* __restrict__ dst,
                              int K, int N, int do_zero) {
    __shared__ float tile[64][33];
    if (do_zero && blockIdx.x == 0 && blockIdx.y == 0 && blockIdx.z == 0 &&
        threadIdx.y == 0 && threadIdx.x < E_NUM)
        g_cnt[threadIdx.x] = 0;
    const int e = blockIdx.z, s = blockIdx.y, n0 = blockIdx.x * 32;
    const int tx = threadIdx.x, ty = threadIdx.y;      // 32 x 8
    const float* sp = src + (size_t)e * K * N + (size_t)s * 64 * N + n0;
#pragma unroll
    for (int dy = 0; dy < 8; dy++)                      // 64 k-rows, coalesced over n
        tile[ty + dy * 8][tx] = sp[(size_t)(ty + dy * 8) * N + tx];
    __syncthreads();
    __half* dp = dst + (((size_t)e * (K / 64) + s) * N + n0) * 64;
    const int nn = n0 + tx;
#pragma unroll
    for (int dy = 0; dy < 4; dy++) {
        int k = (ty + dy * 8) * 2;                      // even k: pair stays in one 16B unit
        __half2 v = __floats2half2_rn(tile[k][tx], tile[k + 1][tx]);
        *(__half2*)(dp + (size_t)tx * 64 + (((k >> 3) ^ (nn & 7)) << 3) + (k & 7)) = v;
    }
}

// ---------------- x -> fp16, and zero the output buffer ----------------
__global__ __launch_bounds__(256) void xcvt_kernel(const float* __restrict__ x,
                                                   float* __restrict__ out) {
    size_t i = ((size_t)blockIdx.x * 256 + threadIdx.x) * 8;
    float4 a = *(const float4*)(x + i);
    float4 b = *(const float4*)(x + i + 4);
    __half2 h[4] = { __floats2half2_rn(a.x, a.y), __floats2half2_rn(a.z, a.w),
                     __floats2half2_rn(b.x, b.y), __floats2half2_rn(b.z, b.w) };
    *(uint4*)(g_xh + i) = *(uint4*)h;
    float4 z = make_float4(0.f, 0.f, 0.f, 0.f);
    *(float4*)(out + i) = z;
    *(float4*)(out + i + 4) = z;
}

// ---------------- gate: logits, top-2, scatter ----------------
__global__ __launch_bounds__(512) void gate_kernel(
    const float* __restrict__ x, const float* __restrict__ gw,
    const float* __restrict__ gb)
{
    __shared__ float gws[E_NUM * D_DIM];
    const int tid = threadIdx.x;
    for (int i = tid; i < E_NUM * D_DIM; i += 512) {
        int e = i >> 10, d = i & 1023;
        gws[i] = gw[d * E_NUM + e];
    }
    __syncthreads();

    const int warp = tid >> 5, lane = tid & 31;
    const int tok0 = blockIdx.x * 64 + warp * 4;

    float acc[4][E_NUM];
#pragma unroll
    for (int t = 0; t < 4; t++)
#pragma unroll
        for (int e = 0; e < E_NUM; e++) acc[t][e] = 0.f;

    const float* xr = x + (size_t)tok0 * D_DIM;
    for (int d = lane; d < D_DIM; d += 32) {
        float xv[4];
#pragma unroll
        for (int t = 0; t < 4; t++) xv[t] = xr[(size_t)t * D_DIM + d];
#pragma unroll
        for (int e = 0; e < E_NUM; e++) {
            float w = gws[e * D_DIM + d];
#pragma unroll
            for (int t = 0; t < 4; t++) acc[t][e] += xv[t] * w;
        }
    }
#pragma unroll
    for (int t = 0; t < 4; t++)
#pragma unroll
        for (int e = 0; e < E_NUM; e++)
#pragma unroll
            for (int s = 16; s; s >>= 1)
                acc[t][e] += __shfl_xor_sync(0xffffffffu, acc[t][e], s);

    if (lane == 0) {
#pragma unroll
        for (int t = 0; t < 4; t++) {
            float l[E_NUM];
#pragma unroll
            for (int e = 0; e < E_NUM; e++) l[e] = acc[t][e] + gb[e];
            int i0 = 0;
#pragma unroll
            for (int e = 1; e < E_NUM; e++) if (l[e] > l[i0]) i0 = e;
            int i1 = (i0 == 0) ? 1 : 0;
#pragma unroll
            for (int e = 0; e < E_NUM; e++) if (e != i0 && l[e] > l[i1]) i1 = e;
            float e1 = expf(l[i1] - l[i0]);
            float s  = 1.0f + e1;
            int tok  = tok0 + t;
            int p0 = atomicAdd(&g_cnt[i0], 1);
            g_tok[i0][p0] = tok * 2 + 0; g_wgt[i0][p0] = 1.0f / s;
            int p1 = atomicAdd(&g_cnt[i1], 1);
            g_tok[i1][p1] = tok * 2 + 1; g_wgt[i1][p1] = e1 / s;
        }
    }
}

// ---------------- E1: h = gelu(x[64,1024] @ w1^T + b1) -> g_h (fp16 mma) ----------------
__global__ void __launch_bounds__(NTHR, 2) expert1_kernel(const float* __restrict__ b1)
{
    const int e     = blockIdx.y;
    const int cnt   = g_cnt[e];
    const int start = blockIdx.x * TM;
    if (start >= cnt) return;

    __shared__ int tids_s[TM];
    __shared__ __align__(8) uint64_t mbar_s[2];
    extern __shared__ __align__(16) char smem[];
    const uint32_t sb = smem_u32(smem);

    const int tid = threadIdx.x;
    if (tid < TM) {
        int src = (tid < cnt - start) ? (start + tid) : start;
        tids_s[tid] = g_tok[e][src] >> 1;
    }
    const uint32_t mb[2] = { smem_u32(&mbar_s[0]), smem_u32(&mbar_s[1]) };
    if (tid == 0) { mbar_init(mb[0], 1); mbar_init(mb[1], 1); }
    __syncthreads();

    const int warp = tid >> 5, lane = tid & 31;
    const int wm = warp & 1, wn = warp >> 1;            // 2(M,32) x 4(N,64)
    const int sub = lane >> 3, rin = lane & 7;
    const int g = lane >> 2, tg = lane & 3;
    const int arl = (sub & 1) * 8 + rin, auo = sub >> 1;
    const int brl = ((sub >> 1) & 1) * 8 + rin, buo = sub & 1;

    const __half* w1h = g_w1h + (size_t)e * 16 * 16384;   // [16 slices][16384 halves]
    const float*  b1e = b1 + e * H_DIM;

    // per-thread A-gather (fp16): 64 rows x 8 units of 16B, 2 cp16/thread/slice
    const int r0 = tid >> 2, u0 = tid & 3, u1 = u0 + 4;
    const __half* ga0 = g_xh + (size_t)tids_s[r0] * D_DIM + u0 * 8;
    const __half* ga1 = g_xh + (size_t)tids_s[r0] * D_DIM + u1 * 8;
    const uint32_t sa0 = r0 * 128 + ((u0 ^ (r0 & 7)) << 4);
    const uint32_t sa1 = r0 * 128 + ((u1 ^ (r0 & 7)) << 4);

    float c[2][8][4];
#pragma unroll
    for (int mi = 0; mi < 2; mi++)
#pragma unroll
        for (int ni = 0; ni < 8; ni++)
#pragma unroll
            for (int q = 0; q < 4; q++) c[mi][ni][q] = 0.f;

    int ph[2] = {0, 0};

    if (tid == 0) { mbar_expect(mb[0], 32768); bulk_g2s(sb + ST_B, w1h, 32768, mb[0]); }
    cp16(sb + sa0, ga0); cp16(sb + sa1, ga1); cp_commit();

    for (int i = 0; i < 16; i++) {                      // 16 slices of k64
        const int b = i & 1;
        cp_wait<0>();
        mbar_wait(mb[b], ph[b]); ph[b] ^= 1;
        __syncthreads();
        if (i + 1 < 16) {
            const int nb = b ^ 1;
            const uint32_t st = sb + nb * ST_SZ;
            if (tid == 0) {
                mbar_expect(mb[nb], 32768);
                bulk_g2s(st + ST_B, w1h + (size_t)(i + 1) * 16384, 32768, mb[nb]);
            }
            cp16(st + sa0, ga0 + (i + 1) * 64);
            cp16(st + sa1, ga1 + (i + 1) * 64);
            cp_commit();
        }
        const uint32_t Ab = sb + b * ST_SZ;
        const uint32_t Bb = Ab + ST_B;
#pragma unroll
        for (int kk = 0; kk < 4; kk++) {                // 4 x k16
            uint32_t a[2][4], bf[4][4];
#pragma unroll
            for (int mi = 0; mi < 2; mi++) {
                int row = wm * 32 + mi * 16 + arl;
                int u   = 2 * kk + auo;
                ldsm4(a[mi], Ab + row * 128 + ((u ^ (row & 7)) << 4));
            }
#pragma unroll
            for (int p = 0; p < 4; p++) {
                int row = wn * 64 + p * 16 + brl;
                int u   = 2 * kk + buo;
                ldsm4(bf[p], Bb + row * 128 + ((u ^ (row & 7)) << 4));
            }
#pragma unroll
            for (int mi = 0; mi < 2; mi++)
#pragma unroll
                for (int ni = 0; ni < 8; ni++)
                    mma16(c[mi][ni], a[mi], &bf[ni >> 1][(ni & 1) * 2]);
        }
    }
    __syncthreads();   // ring dead; reuse as h staging [64][272] halves

    // bias + exact gelu -> staging fp16
#pragma unroll
    for (int mi = 0; mi < 2; mi++) {
#pragma unroll
        for (int ni = 0; ni < 8; ni++) {
            int col = wn * 64 + ni * 8 + tg * 2;
            float bb0 = b1e[col], bb1 = b1e[col + 1];
#pragma unroll
            for (int h = 0; h < 2; h++) {
                int row = wm * 32 + mi * 16 + g + h * 8;
                float v0 = c[mi][ni][h * 2]     + bb0;
                float v1 = c[mi][ni][h * 2 + 1] + bb1;
                v0 = 0.5f * v0 * (1.0f + erff(v0 * 0.70710678f));
                v1 = 0.5f * v1 * (1.0f + erff(v1 * 0.70710678f));
                __half2 hv = __floats2half2_rn(v0, v1);
                asm volatile("st.shared.b32 [%0],%1;"
                             :: "r"(sb + (row * 272 + col) * 2), "r"(*(uint32_t*)&hv));
            }
        }
    }
    __syncthreads();

    // coalesced copy staging -> g_h (64 rows x 512B)
    __half* hdst = g_h + ((size_t)e * B_TOK + start) * H_DIM;
#pragma unroll
    for (int t = 0; t < 8; t++) {
        int ch = tid + t * NTHR;                        // 2048 uint4
        int row = ch >> 5, c4 = ch & 31;
        uint4 v;
        asm volatile("ld.shared.v4.b32 {%0,%1,%2,%3},[%4];"
                     : "=r"(v.x), "=r"(v.y), "=r"(v.z), "=r"(v.w)
                     : "r"(sb + row * 544 + c4 * 16));
        *(uint4*)(hdst + (size_t)row * H_DIM + c4 * 8) = v;
    }
}

// ---------------- E2: out += wt*(h[64,256] @ w2^T panel + b2), fp16 mma ----------------
__global__ void __launch_bounds__(NTHR, 2) expert2_kernel(
    const float* __restrict__ b2, float* __restrict__ out)
{
    const int e     = blockIdx.z;
    const int py    = blockIdx.y;
    const int cnt   = g_cnt[e];
    const int start = blockIdx.x * TM;
    if (start >= cnt) return;
    const int mcount = min(TM, cnt - start);

    __shared__ int   tids_s[TM];
    __shared__ float wts_s[TM];
    __shared__ __align__(8) uint64_t mbar_s[2];
    extern __shared__ __align__(16) char smem[];
    const uint32_t sb = smem_u32(smem);

    const int tid = threadIdx.x;
    if (tid < TM) {
        bool v = tid < mcount;
        int  src = v ? (start + tid) : start;
        tids_s[tid] = g_tok[e][src] >> 1;
        wts_s[tid]  = v ? g_wgt[e][src] : 0.f;
    }
    const uint32_t mb[2] = { smem_u32(&mbar_s[0]), smem_u32(&mbar_s[1]) };
    if (tid == 0) { mbar_init(mb[0], 1); mbar_init(mb[1], 1); }
    __syncthreads();

    const int warp = tid >> 5, lane = tid & 31;
    const int wm = warp & 1, wn = warp >> 1;
    const int sub = lane >> 3, rin = lane & 7;
    const int g = lane >> 2, tg = lane & 3;
    const int arl = (sub & 1) * 8 + rin, auo = sub >> 1;
    const int brl = ((sub >> 1) & 1) * 8 + rin, buo = sub & 1;

    // w2h: [e][4 slices][1024 n][64]; panel py = 256 n-rows
    const __half* w2h = g_w2h + (size_t)e * 4 * 65536 + (size_t)py * 256 * 64;
    const float*  b2e = b2 + e * D_DIM + py * 256;

    const int r0 = tid >> 2, u0 = tid & 3, u1 = u0 + 4;
    const __half* ha0 = g_h + ((size_t)e * B_TOK + start + r0) * H_DIM + u0 * 8;
    const __half* ha1 = ha0 + 32;
    const uint32_t sa0 = r0 * 128 + ((u0 ^ (r0 & 7)) << 4);
    const uint32_t sa1 = r0 * 128 + ((u1 ^ (r0 & 7)) << 4);

    float c[2][8][4];
#pragma unroll
    for (int mi = 0; mi < 2; mi++)
#pragma unroll
        for (int ni = 0; ni < 8; ni++)
#pragma unroll
            for (int q = 0; q < 4; q++) c[mi][ni][q] = 0.f;

    int ph[2] = {0, 0};

    if (tid == 0) { mbar_expect(mb[0], 32768); bulk_g2s(sb + ST_B, w2h, 32768, mb[0]); }
    cp16(sb + sa0, ha0); cp16(sb + sa1, ha1); cp_commit();

    for (int i = 0; i < 4; i++) {                       // 4 slices of k64
        const int b = i & 1;
        cp_wait<0>();
        mbar_wait(mb[b], ph[b]); ph[b] ^= 1;
        __syncthreads();
        if (i + 1 < 4) {
            const int nb = b ^ 1;
            const uint32_t st = sb + nb * ST_SZ;
            if (tid == 0) {
                mbar_expect(mb[nb], 32768);
                bulk_g2s(st + ST_B, w2h + (size_t)(i + 1) * 65536, 32768, mb[nb]);
            }
            cp16(st + sa0, ha0 + (i + 1) * 64);
            cp16(st + sa1, ha1 + (i + 1) * 64);
            cp_commit();
        }
        const uint32_t Ab = sb + b * ST_SZ;
        const uint32_t Bb = Ab + ST_B;
#pragma unroll
        for (int kk = 0; kk < 4; kk++) {
            uint32_t a[2][4], bf[4][4];
#pragma unroll
            for (int mi = 0; mi < 2; mi++) {
                int row = wm * 32 + mi * 16 + arl;
                int u   = 2 * kk + auo;
                ldsm4(a[mi], Ab + row * 128 + ((u ^ (row & 7)) << 4));
            }
#pragma unroll
            for (int p = 0; p < 4; p++) {
                int row = wn * 64 + p * 16 + brl;
                int u   = 2 * kk + buo;
                ldsm4(bf[p], Bb + row * 128 + ((u ^ (row & 7)) << 4));
            }
#pragma unroll
            for (int mi = 0; mi < 2; mi++)
#pragma unroll
                for (int ni = 0; ni < 8; ni++)
                    mma16(c[mi][ni], a[mi], &bf[ni >> 1][(ni & 1) * 2]);
        }
    }

    // weighted atomic accumulate into out (fp32 add is commutative -> deterministic)
#pragma unroll
    for (int mi = 0; mi < 2; mi++) {
#pragma unroll
        for (int h = 0; h < 2; h++) {
            int r = wm * 32 + mi * 16 + g + h * 8;
            if (r < mcount) {
                float wt  = wts_s[r];
                float* dst = out + (size_t)tids_s[r] * D_DIM + py * 256;
#pragma unroll
                for (int ni = 0; ni < 8; ni++) {
                    int col = wn * 64 + ni * 8 + tg * 2;
                    atomicAdd(dst + col,     wt * (c[mi][ni][h * 2]     + b2e[col]));
                    atomicAdd(dst + col + 1, wt * (c[mi][ni][h * 2 + 1] + b2e[col + 1]));
                }
            }
        }
    }
}

// ---------------- launch ----------------
extern "C" void kernel_launch(void* const* d_in, const int* in_sizes, int n_in,
                              void* d_out, int out_size) {
    const float* x  = (const float*)d_in[0];
    const float* gw = (const float*)d_in[1];
    const float* gb = (const float*)d_in[2];
    const float* w1 = (const float*)d_in[3];
    const float* b1 = (const float*)d_in[4];
    const float* w2 = (const float*)d_in[5];
    const float* b2 = (const float*)d_in[6];
    float* out = (float*)d_out;

    static __half* w1h_ptr = nullptr;
    static __half* w2h_ptr = nullptr;
    if (!w1h_ptr) {
        cudaGetSymbolAddress((void**)&w1h_ptr, g_w1h);
        cudaGetSymbolAddress((void**)&w2h_ptr, g_w2h);
        cudaFuncSetAttribute(expert1_kernel,
                             cudaFuncAttributeMaxDynamicSharedMemorySize, DYN_SMEM);
        cudaFuncSetAttribute(expert2_kernel,
                             cudaFuncAttributeMaxDynamicSharedMemorySize, DYN_SMEM);
    }

    // w1 [e][D][H]: K=D,N=H ; w2 [e][H][D]: K=H,N=D
    prep_w_kernel<<<dim3(H_DIM / 32, D_DIM / 64, E_NUM), dim3(32, 8)>>>(
        w1, w1h_ptr, D_DIM, H_DIM, 1);
    prep_w_kernel<<<dim3(D_DIM / 32, H_DIM / 64, E_NUM), dim3(32, 8)>>>(
        w2, w2h_ptr, H_DIM, D_DIM, 0);
    xcvt_kernel<<<(int)((size_t)B_TOK * D_DIM / 2048), 256>>>(x, out);
    gate_kernel<<<B_TOK / 64, 512>>>(x, gw, gb);
    expert1_kernel<<<dim3(B_TOK / TM, E_NUM), NTHR, DYN_SMEM>>>(b1);
    expert2_kernel<<<dim3(B_TOK / TM, 4, E_NUM), NTHR, DYN_SMEM>>>(b2, out);
}

// round 9
// speedup vs baseline: 1.4229x; 1.0330x over previous
#include <cuda_runtime.h>
#include <cuda_fp16.h>
#include <math.h>
#include <stdint.h>

#define B_TOK 16384
#define D_DIM 1024
#define H_DIM 256
#define E_NUM 8
#define TM    64
#define NTHR  256

// 2-stage ring: stage = A(64 rows x 128B = 8KB) @0 + B(256 rows x 128B = 32KB) @8192
#define ST_SZ   40960
#define ST_B    8192
#define DYN_SMEM 81920

// ---------------- device scratch ----------------
__device__ int    g_cnt[E_NUM];
__device__ int    g_tok[E_NUM][B_TOK];          // tok*2 + rank
__device__ float  g_wgt[E_NUM][B_TOK];
__device__ __half g_xh[(size_t)B_TOK * D_DIM];                 // x fp16
// tiled + pre-swizzled fp16 weights: [e][slice(k64)][n][64 halves swizzled]
__device__ __half g_w1h[(size_t)E_NUM * H_DIM * D_DIM];
__device__ __half g_w2h[(size_t)E_NUM * D_DIM * H_DIM];
__device__ __half g_h[(size_t)E_NUM * B_TOK * H_DIM];          // gelu(h) fp16

// ---------------- helpers ----------------
__device__ __forceinline__ uint32_t smem_u32(const void* p) {
    uint32_t r;
    asm("{.reg .u64 t; cvta.to.shared.u64 t,%1; cvt.u32.u64 %0,t;}" : "=r"(r) : "l"(p));
    return r;
}
__device__ __forceinline__ void cp16(uint32_t s, const void* g) {
    asm volatile("cp.async.cg.shared.global [%0],[%1],16;" :: "r"(s), "l"(g));
}
__device__ __forceinline__ void cp_commit() {
    asm volatile("cp.async.commit_group;" ::: "memory");
}
template <int N> __device__ __forceinline__ void cp_wait() {
    asm volatile("cp.async.wait_group %0;" :: "n"(N) : "memory");
}
__device__ __forceinline__ void mbar_init(uint32_t mb, uint32_t cnt) {
    asm volatile("mbarrier.init.shared.b64 [%0], %1;" :: "r"(mb), "r"(cnt) : "memory");
}
__device__ __forceinline__ void mbar_expect(uint32_t mb, uint32_t bytes) {
    asm volatile("mbarrier.arrive.expect_tx.shared.b64 _, [%0], %1;"
                 :: "r"(mb), "r"(bytes) : "memory");
}
__device__ __forceinline__ void bulk_g2s(uint32_t dst, const void* src,
                                         uint32_t bytes, uint32_t mb) {
    asm volatile(
        "cp.async.bulk.shared::cluster.global.mbarrier::complete_tx::bytes "
        "[%0], [%1], %2, [%3];"
        :: "r"(dst), "l"(src), "r"(bytes), "r"(mb) : "memory");
}
__device__ __forceinline__ void mbar_wait(uint32_t mb, uint32_t ph) {
    asm volatile(
        "{.reg .pred P;\n\t"
        "WL%=:\n\t"
        "mbarrier.try_wait.parity.acquire.cta.shared::cta.b64 P,[%0],%1,0x989680;\n\t"
        "@P bra WD%=;\n\t"
        "bra WL%=;\n\t"
        "WD%=:}" :: "r"(mb), "r"(ph) : "memory");
}
__device__ __forceinline__ void ldsm4(uint32_t* r, uint32_t a) {
    asm volatile("ldmatrix.sync.aligned.m8n8.x4.shared.b16 {%0,%1,%2,%3},[%4];"
                 : "=r"(r[0]), "=r"(r[1]), "=r"(r[2]), "=r"(r[3]) : "r"(a));
}
// m16n8k16 fp16 mma, fp32 accum
__device__ __forceinline__ void mma16(float* c, const uint32_t* a, const uint32_t* b) {
    asm volatile(
        "mma.sync.aligned.m16n8k16.row.col.f32.f16.f16.f32 "
        "{%0,%1,%2,%3},{%4,%5,%6,%7},{%8,%9},{%0,%1,%2,%3};"
        : "+f"(c[0]), "+f"(c[1]), "+f"(c[2]), "+f"(c[3])
        : "r"(a[0]), "r"(a[1]), "r"(a[2]), "r"(a[3]), "r"(b[0]), "r"(b[1]));
}

// ---------------- weight prep: [E][K][N] fp32 -> [e][k/64][n][64] fp16 swizzled ----------------
__global__ void prep_w_kernel(const float* __restrict__ src, __half* __restrict__ dst,
                              int K, int N, int do_zero) {
    __shared__ float tile[64][33];
    if (do_zero && blockIdx.x == 0 && blockIdx.y == 0 && blockIdx.z == 0 &&
        threadIdx.y == 0 && threadIdx.x < E_NUM)
        g_cnt[threadIdx.x] = 0;
    const int e = blockIdx.z, s = blockIdx.y, n0 = blockIdx.x * 32;
    const int tx = threadIdx.x, ty = threadIdx.y;      // 32 x 8
    const float* sp = src + (size_t)e * K * N + (size_t)s * 64 * N + n0;
#pragma unroll
    for (int dy = 0; dy < 8; dy++)
        tile[ty + dy * 8][tx] = sp[(size_t)(ty + dy * 8) * N + tx];
    __syncthreads();
    __half* dp = dst + (((size_t)e * (K / 64) + s) * N + n0) * 64;
    const int nn = n0 + tx;
#pragma unroll
    for (int dy = 0; dy < 4; dy++) {
        int k = (ty + dy * 8) * 2;
        __half2 v = __floats2half2_rn(tile[k][tx], tile[k + 1][tx]);
        *(__half2*)(dp + (size_t)tx * 64 + (((k >> 3) ^ (nn & 7)) << 3) + (k & 7)) = v;
    }
}

// ---------------- gate: logits + top-2 + scatter + x->fp16 + zero out ----------------
__global__ __launch_bounds__(512) void gate_kernel(
    const float* __restrict__ x, const float* __restrict__ gw,
    const float* __restrict__ gb, float* __restrict__ out)
{
    __shared__ float gws[E_NUM * D_DIM];   // [e][d], 32KB
    const int tid = threadIdx.x;
    for (int i = tid; i < E_NUM * D_DIM; i += 512) {
        int e = i >> 10, d = i & 1023;
        gws[i] = gw[d * E_NUM + e];
    }
    {   // zero this block's 64 output rows (poisoned by harness)
        float4 z = make_float4(0.f, 0.f, 0.f, 0.f);
        float4* o4 = (float4*)(out + (size_t)blockIdx.x * 64 * D_DIM);
        for (int i = tid; i < 64 * D_DIM / 4; i += 512) o4[i] = z;
    }
    __syncthreads();

    const int warp = tid >> 5, lane = tid & 31;
    const int tok0 = blockIdx.x * 64 + warp * 4;       // 4 tokens per warp
    const int d0 = lane * 4;

    const float* xr = x    + (size_t)tok0 * D_DIM;
    __half*      xh = g_xh + (size_t)tok0 * D_DIM;

    float acc[4][E_NUM];
#pragma unroll
    for (int t = 0; t < 4; t++)
#pragma unroll
        for (int e = 0; e < E_NUM; e++) acc[t][e] = 0.f;

    float4 cur[4], nxt[4];
#pragma unroll
    for (int t = 0; t < 4; t++) cur[t] = *(const float4*)(xr + (size_t)t * D_DIM + d0);

#pragma unroll
    for (int j = 0; j < 8; j++) {                      // 8 chunks of 128 floats
        const int dj = j * 128 + d0;
        if (j < 7) {
#pragma unroll
            for (int t = 0; t < 4; t++)
                nxt[t] = *(const float4*)(xr + (size_t)t * D_DIM + dj + 128);
        }
#pragma unroll
        for (int e = 0; e < E_NUM; e++) {
            float4 wv = *(const float4*)&gws[e * D_DIM + dj];
#pragma unroll
            for (int t = 0; t < 4; t++)
                acc[t][e] += cur[t].x * wv.x + cur[t].y * wv.y
                           + cur[t].z * wv.z + cur[t].w * wv.w;
        }
#pragma unroll
        for (int t = 0; t < 4; t++) {                  // fp16 convert + store (8B)
            __half2 h0 = __floats2half2_rn(cur[t].x, cur[t].y);
            __half2 h1 = __floats2half2_rn(cur[t].z, cur[t].w);
            uint2 u = make_uint2(*(uint32_t*)&h0, *(uint32_t*)&h1);
            *(uint2*)(xh + (size_t)t * D_DIM + dj) = u;
        }
#pragma unroll
        for (int t = 0; t < 4; t++) cur[t] = nxt[t];
    }

#pragma unroll
    for (int t = 0; t < 4; t++)
#pragma unroll
        for (int e = 0; e < E_NUM; e++)
#pragma unroll
            for (int s = 16; s; s >>= 1)
                acc[t][e] += __shfl_xor_sync(0xffffffffu, acc[t][e], s);

    if (lane == 0) {
#pragma unroll
        for (int t = 0; t < 4; t++) {
            float l[E_NUM];
#pragma unroll
            for (int e = 0; e < E_NUM; e++) l[e] = acc[t][e] + gb[e];
            int i0 = 0;
#pragma unroll
            for (int e = 1; e < E_NUM; e++) if (l[e] > l[i0]) i0 = e;
            int i1 = (i0 == 0) ? 1 : 0;
#pragma unroll
            for (int e = 0; e < E_NUM; e++) if (e != i0 && l[e] > l[i1]) i1 = e;
            float e1 = expf(l[i1] - l[i0]);
            float s  = 1.0f + e1;
            int tok  = tok0 + t;
            int p0 = atomicAdd(&g_cnt[i0], 1);
            g_tok[i0][p0] = tok * 2 + 0; g_wgt[i0][p0] = 1.0f / s;
            int p1 = atomicAdd(&g_cnt[i1], 1);
            g_tok[i1][p1] = tok * 2 + 1; g_wgt[i1][p1] = e1 / s;
        }
    }
}

// ---------------- E1: h = gelu(x[64,1024] @ w1^T + b1) -> g_h (fp16 mma) ----------------
__global__ void __launch_bounds__(NTHR, 2) expert1_kernel(const float* __restrict__ b1)
{
    const int e     = blockIdx.y;
    const int cnt   = g_cnt[e];
    const int start = blockIdx.x * TM;
    if (start >= cnt) return;

    __shared__ int tids_s[TM];
    __shared__ __align__(8) uint64_t mbar_s[2];
    extern __shared__ __align__(16) char smem[];
    const uint32_t sb = smem_u32(smem);

    const int tid = threadIdx.x;
    if (tid < TM) {
        int src = (tid < cnt - start) ? (start + tid) : start;
        tids_s[tid] = g_tok[e][src] >> 1;
    }
    const uint32_t mb[2] = { smem_u32(&mbar_s[0]), smem_u32(&mbar_s[1]) };
    if (tid == 0) { mbar_init(mb[0], 1); mbar_init(mb[1], 1); }
    __syncthreads();

    const int warp = tid >> 5, lane = tid & 31;
    const int wm = warp & 1, wn = warp >> 1;
    const int sub = lane >> 3, rin = lane & 7;
    const int g = lane >> 2, tg = lane & 3;
    const int arl = (sub & 1) * 8 + rin, auo = sub >> 1;
    const int brl = ((sub >> 1) & 1) * 8 + rin, buo = sub & 1;

    const __half* w1h = g_w1h + (size_t)e * 16 * 16384;
    const float*  b1e = b1 + e * H_DIM;

    const int r0 = tid >> 2, u0 = tid & 3, u1 = u0 + 4;
    const __half* ga0 = g_xh + (size_t)tids_s[r0] * D_DIM + u0 * 8;
    const __half* ga1 = g_xh + (size_t)tids_s[r0] * D_DIM + u1 * 8;
    const uint32_t sa0 = r0 * 128 + ((u0 ^ (r0 & 7)) << 4);
    const uint32_t sa1 = r0 * 128 + ((u1 ^ (r0 & 7)) << 4);

    float c[2][8][4];
#pragma unroll
    for (int mi = 0; mi < 2; mi++)
#pragma unroll
        for (int ni = 0; ni < 8; ni++)
#pragma unroll
            for (int q = 0; q < 4; q++) c[mi][ni][q] = 0.f;

    int ph[2] = {0, 0};

    if (tid == 0) { mbar_expect(mb[0], 32768); bulk_g2s(sb + ST_B, w1h, 32768, mb[0]); }
    cp16(sb + sa0, ga0); cp16(sb + sa1, ga1); cp_commit();

    for (int i = 0; i < 16; i++) {
        const int b = i & 1;
        cp_wait<0>();
        mbar_wait(mb[b], ph[b]); ph[b] ^= 1;
        __syncthreads();
        if (i + 1 < 16) {
            const int nb = b ^ 1;
            const uint32_t st = sb + nb * ST_SZ;
            if (tid == 0) {
                mbar_expect(mb[nb], 32768);
                bulk_g2s(st + ST_B, w1h + (size_t)(i + 1) * 16384, 32768, mb[nb]);
            }
            cp16(st + sa0, ga0 + (i + 1) * 64);
            cp16(st + sa1, ga1 + (i + 1) * 64);
            cp_commit();
        }
        const uint32_t Ab = sb + b * ST_SZ;
        const uint32_t Bb = Ab + ST_B;
#pragma unroll
        for (int kk = 0; kk < 4; kk++) {
            uint32_t a[2][4], bf[4][4];
#pragma unroll
            for (int mi = 0; mi < 2; mi++) {
                int row = wm * 32 + mi * 16 + arl;
                int u   = 2 * kk + auo;
                ldsm4(a[mi], Ab + row * 128 + ((u ^ (row & 7)) << 4));
            }
#pragma unroll
            for (int p = 0; p < 4; p++) {
                int row = wn * 64 + p * 16 + brl;
                int u   = 2 * kk + buo;
                ldsm4(bf[p], Bb + row * 128 + ((u ^ (row & 7)) << 4));
            }
#pragma unroll
            for (int mi = 0; mi < 2; mi++)
#pragma unroll
                for (int ni = 0; ni < 8; ni++)
                    mma16(c[mi][ni], a[mi], &bf[ni >> 1][(ni & 1) * 2]);
        }
    }
    __syncthreads();   // ring dead; reuse as h staging [64][272] halves

#pragma unroll
    for (int mi = 0; mi < 2; mi++) {
#pragma unroll
        for (int ni = 0; ni < 8; ni++) {
            int col = wn * 64 + ni * 8 + tg * 2;
            float bb0 = b1e[col], bb1 = b1e[col + 1];
#pragma unroll
            for (int h = 0; h < 2; h++) {
                int row = wm * 32 + mi * 16 + g + h * 8;
                float v0 = c[mi][ni][h * 2]     + bb0;
                float v1 = c[mi][ni][h * 2 + 1] + bb1;
                v0 = 0.5f * v0 * (1.0f + erff(v0 * 0.70710678f));
                v1 = 0.5f * v1 * (1.0f + erff(v1 * 0.70710678f));
                __half2 hv = __floats2half2_rn(v0, v1);
                asm volatile("st.shared.b32 [%0],%1;"
                             :: "r"(sb + (row * 272 + col) * 2), "r"(*(uint32_t*)&hv));
            }
        }
    }
    __syncthreads();

    __half* hdst = g_h + ((size_t)e * B_TOK + start) * H_DIM;
#pragma unroll
    for (int t = 0; t < 8; t++) {
        int ch = tid + t * NTHR;
        int row = ch >> 5, c4 = ch & 31;
        uint4 v;
        asm volatile("ld.shared.v4.b32 {%0,%1,%2,%3},[%4];"
                     : "=r"(v.x), "=r"(v.y), "=r"(v.z), "=r"(v.w)
                     : "r"(sb + row * 544 + c4 * 16));
        *(uint4*)(hdst + (size_t)row * H_DIM + c4 * 8) = v;
    }
}

// ---------------- E2: out += wt*(h[64,256] @ w2^T panel + b2), fp16 mma ----------------
__global__ void __launch_bounds__(NTHR, 2) expert2_kernel(
    const float* __restrict__ b2, float* __restrict__ out)
{
    const int e     = blockIdx.z;
    const int py    = blockIdx.y;
    const int cnt   = g_cnt[e];
    const int start = blockIdx.x * TM;
    if (start >= cnt) return;
    const int mcount = min(TM, cnt - start);

    __shared__ int   tids_s[TM];
    __shared__ float wts_s[TM];
    __shared__ __align__(8) uint64_t mbar_s[2];
    extern __shared__ __align__(16) char smem[];
    const uint32_t sb = smem_u32(smem);

    const int tid = threadIdx.x;
    if (tid < TM) {
        bool v = tid < mcount;
        int  src = v ? (start + tid) : start;
        tids_s[tid] = g_tok[e][src] >> 1;
        wts_s[tid]  = v ? g_wgt[e][src] : 0.f;
    }
    const uint32_t mb[2] = { smem_u32(&mbar_s[0]), smem_u32(&mbar_s[1]) };
    if (tid == 0) { mbar_init(mb[0], 1); mbar_init(mb[1], 1); }
    __syncthreads();

    const int warp = tid >> 5, lane = tid & 31;
    const int wm = warp & 1, wn = warp >> 1;
    const int sub = lane >> 3, rin = lane & 7;
    const int g = lane >> 2, tg = lane & 3;
    const int arl = (sub & 1) * 8 + rin, auo = sub >> 1;
    const int brl = ((sub >> 1) & 1) * 8 + rin, buo = sub & 1;

    const __half* w2h = g_w2h + (size_t)e * 4 * 65536 + (size_t)py * 256 * 64;
    const float*  b2e = b2 + e * D_DIM + py * 256;

    const int r0 = tid >> 2, u0 = tid & 3, u1 = u0 + 4;
    const __half* ha0 = g_h + ((size_t)e * B_TOK + start + r0) * H_DIM + u0 * 8;
    const __half* ha1 = ha0 + 32;
    const uint32_t sa0 = r0 * 128 + ((u0 ^ (r0 & 7)) << 4);
    const uint32_t sa1 = r0 * 128 + ((u1 ^ (r0 & 7)) << 4);

    float c[2][8][4];
#pragma unroll
    for (int mi = 0; mi < 2; mi++)
#pragma unroll
        for (int ni = 0; ni < 8; ni++)
#pragma unroll
            for (int q = 0; q < 4; q++) c[mi][ni][q] = 0.f;

    int ph[2] = {0, 0};

    if (tid == 0) { mbar_expect(mb[0], 32768); bulk_g2s(sb + ST_B, w2h, 32768, mb[0]); }
    cp16(sb + sa0, ha0); cp16(sb + sa1, ha1); cp_commit();

    for (int i = 0; i < 4; i++) {
        const int b = i & 1;
        cp_wait<0>();
        mbar_wait(mb[b], ph[b]); ph[b] ^= 1;
        __syncthreads();
        if (i + 1 < 4) {
            const int nb = b ^ 1;
            const uint32_t st = sb + nb * ST_SZ;
            if (tid == 0) {
                mbar_expect(mb[nb], 32768);
                bulk_g2s(st + ST_B, w2h + (size_t)(i + 1) * 65536, 32768, mb[nb]);
            }
            cp16(st + sa0, ha0 + (i + 1) * 64);
            cp16(st + sa1, ha1 + (i + 1) * 64);
            cp_commit();
        }
        const uint32_t Ab = sb + b * ST_SZ;
        const uint32_t Bb = Ab + ST_B;
#pragma unroll
        for (int kk = 0; kk < 4; kk++) {
            uint32_t a[2][4], bf[4][4];
#pragma unroll
            for (int mi = 0; mi < 2; mi++) {
                int row = wm * 32 + mi * 16 + arl;
                int u   = 2 * kk + auo;
                ldsm4(a[mi], Ab + row * 128 + ((u ^ (row & 7)) << 4));
            }
#pragma unroll
            for (int p = 0; p < 4; p++) {
                int row = wn * 64 + p * 16 + brl;
                int u   = 2 * kk + buo;
                ldsm4(bf[p], Bb + row * 128 + ((u ^ (row & 7)) << 4));
            }
#pragma unroll
            for (int mi = 0; mi < 2; mi++)
#pragma unroll
                for (int ni = 0; ni < 8; ni++)
                    mma16(c[mi][ni], a[mi], &bf[ni >> 1][(ni & 1) * 2]);
        }
    }

#pragma unroll
    for (int mi = 0; mi < 2; mi++) {
#pragma unroll
        for (int h = 0; h < 2; h++) {
            int r = wm * 32 + mi * 16 + g + h * 8;
            if (r < mcount) {
                float wt  = wts_s[r];
                float* dst = out + (size_t)tids_s[r] * D_DIM + py * 256;
#pragma unroll
                for (int ni = 0; ni < 8; ni++) {
                    int col = wn * 64 + ni * 8 + tg * 2;
                    atomicAdd(dst + col,     wt * (c[mi][ni][h * 2]     + b2e[col]));
                    atomicAdd(dst + col + 1, wt * (c[mi][ni][h * 2 + 1] + b2e[col + 1]));
                }
            }
        }
    }
}

// ---------------- launch ----------------
extern "C" void kernel_launch(void* const* d_in, const int* in_sizes, int n_in,
                              void* d_out, int out_size) {
    const float* x  = (const float*)d_in[0];
    const float* gw = (const float*)d_in[1];
    const float* gb = (const float*)d_in[2];
    const float* w1 = (const float*)d_in[3];
    const float* b1 = (const float*)d_in[4];
    const float* w2 = (const float*)d_in[5];
    const float* b2 = (const float*)d_in[6];
    float* out = (float*)d_out;

    static __half* w1h_ptr = nullptr;
    static __half* w2h_ptr = nullptr;
    if (!w1h_ptr) {
        cudaGetSymbolAddress((void**)&w1h_ptr, g_w1h);
        cudaGetSymbolAddress((void**)&w2h_ptr, g_w2h);
        cudaFuncSetAttribute(expert1_kernel,
                             cudaFuncAttributeMaxDynamicSharedMemorySize, DYN_SMEM);
        cudaFuncSetAttribute(expert2_kernel,
                             cudaFuncAttributeMaxDynamicSharedMemorySize, DYN_SMEM);
    }

    prep_w_kernel<<<dim3(H_DIM / 32, D_DIM / 64, E_NUM), dim3(32, 8)>>>(
        w1, w1h_ptr, D_DIM, H_DIM, 1);
    prep_w_kernel<<<dim3(D_DIM / 32, H_DIM / 64, E_NUM), dim3(32, 8)>>>(
        w2, w2h_ptr, H_DIM, D_DIM, 0);
    gate_kernel<<<B_TOK / 64, 512>>>(x, gw, gb, out);
    expert1_kernel<<<dim3(B_TOK / TM, E_NUM), NTHR, DYN_SMEM>>>(b1);
    expert2_kernel<<<dim3(B_TOK / TM, 4, E_NUM), NTHR, DYN_SMEM>>>(b2, out);
}